// round 15
// baseline (speedup 1.0000x reference)
#include <cuda_runtime.h>
#include <cuda_bf16.h>
#include <cstdint>

#define Bdim 256
#define Ddim 128
#define Cdim 8000
#define CPAD 8064
#define SCALE_F 64.0f
#define MARGIN_F 0.5f
#define EPS_F 1e-12f
#define NCONS 126     // grid (63 x 2); 1 CTA/SM, 148 SMs -> all co-resident
#define NTHR 512

// ---------------- device scratch (no allocations allowed) ----------------
// All sync counters are monotonic (never reset) -> graph-replay safe.
__device__ uint4 g_neHi4[Bdim * 16];   // row = b, 16 x 16B of bf16 along k
__device__ uint4 g_neLo4[Bdim * 16];
__device__ uint4 g_grHi4[Bdim * 16];
__device__ float g_s[Bdim];
__device__ float g_part[2 * 63 * 128]; // per-(y,x) rowsum partials (slot writes)
__device__ unsigned int g_entry;       // epoch: 126 entries per launch
__device__ unsigned int g_prepY[2];    // per-y prep rows done: 128 per launch
__device__ unsigned int g_bar;         // rowsum barrier: 126 per launch

// ---------------- warp-MMA helpers (family-safe: ldmatrix + mma.sync) -------
__device__ __forceinline__ uint32_t smem_u32(const void* p) {
    uint32_t a;
    asm("{ .reg .u64 t; cvta.to.shared.u64 t, %1; cvt.u32.u64 %0, t; }"
        : "=r"(a) : "l"(p));
    return a;
}
__device__ __forceinline__ void ldsm_x4(uint32_t& r0, uint32_t& r1,
                                        uint32_t& r2, uint32_t& r3,
                                        uint32_t addr) {
    asm volatile(
        "ldmatrix.sync.aligned.m8n8.x4.shared.b16 {%0,%1,%2,%3}, [%4];"
        : "=r"(r0), "=r"(r1), "=r"(r2), "=r"(r3) : "r"(addr));
}
__device__ __forceinline__ void mma16816(float* d, const uint32_t* a,
                                         const uint32_t* b) {
    asm volatile(
        "mma.sync.aligned.m16n8k16.row.col.f32.bf16.bf16.f32 "
        "{%0,%1,%2,%3}, {%4,%5,%6,%7}, {%8,%9}, {%0,%1,%2,%3};"
        : "+f"(d[0]), "+f"(d[1]), "+f"(d[2]), "+f"(d[3])
        : "r"(a[0]), "r"(a[1]), "r"(a[2]), "r"(a[3]), "r"(b[0]), "r"(b[1]));
}
__device__ __forceinline__ uint32_t bf16pair(float v0, float v1) {
    __nv_bfloat16 h0 = __float2bfloat16(v0);
    __nv_bfloat16 h1 = __float2bfloat16(v1);
    return (uint32_t)__bfloat16_as_ushort(h0) |
           ((uint32_t)__bfloat16_as_ushort(h1) << 16);
}

// smem tile geometry: 128 rows x 136 bf16 (272B rows -> 4-bank shift per row)
#define ROW_U4 17
#define TILE_U4 (128 * ROW_U4)           // 2176 uint4 = 34816 B
// layout: 0 neHi, 1 neLo, 2 grHi, 3 nwHi, 4 nwLo  (5 tiles = 174080 B)

// ---------------- distributed prep: one warp handles one b-row --------------
// Publishes its row to g_prepY[row>>7] IMMEDIATELY (per-warp fence+atomic),
// so consumers' wait is gated by gather latency, not by CTA-wide barriers.
__device__ __forceinline__ void prep_row(int bb, int lane,
                                         const float* __restrict__ embds,
                                         const float* __restrict__ w,
                                         const int* __restrict__ labels) {
    float4 e4 = ((const float4*)embds)[bb * 32 + lane];
    int lb = labels[bb];
    const float* wc = w + lb;
    float g0 = wc[(size_t)(4 * lane + 0) * Cdim];
    float g1 = wc[(size_t)(4 * lane + 1) * Cdim];
    float g2 = wc[(size_t)(4 * lane + 2) * Cdim];
    float g3 = wc[(size_t)(4 * lane + 3) * Cdim];
    float ss = e4.x * e4.x + e4.y * e4.y + e4.z * e4.z + e4.w * e4.w;
    float ss2 = g0 * g0 + g1 * g1 + g2 * g2 + g3 * g3;
#pragma unroll
    for (int o = 16; o > 0; o >>= 1) {
        ss += __shfl_xor_sync(0xffffffffu, ss, o);
        ss2 += __shfl_xor_sync(0xffffffffu, ss2, o);
    }
    float rne = rsqrtf(fmaxf(ss, EPS_F));
    float rgr = rsqrtf(fmaxf(ss2, EPS_F));
    float n0 = e4.x * rne, n1 = e4.y * rne, n2 = e4.z * rne, n3 = e4.w * rne;
    float q0 = g0 * rgr, q1 = g1 * rgr, q2 = g2 * rgr, q3 = g3 * rgr;
    float sp = n0 * q0 + n1 * q1 + n2 * q2 + n3 * q3;
#pragma unroll
    for (int o = 16; o > 0; o >>= 1) sp += __shfl_xor_sync(0xffffffffu, sp, o);
    if (lane == 0) g_s[bb] = sp;
    __nv_bfloat16 h0 = __float2bfloat16(n0);
    __nv_bfloat16 h1 = __float2bfloat16(n1);
    __nv_bfloat16 h2 = __float2bfloat16(n2);
    __nv_bfloat16 h3 = __float2bfloat16(n3);
    uint2 nh, nl, gh;
    nh.x = (uint32_t)__bfloat16_as_ushort(h0) |
           ((uint32_t)__bfloat16_as_ushort(h1) << 16);
    nh.y = (uint32_t)__bfloat16_as_ushort(h2) |
           ((uint32_t)__bfloat16_as_ushort(h3) << 16);
    nl.x = bf16pair(n0 - __bfloat162float(h0), n1 - __bfloat162float(h1));
    nl.y = bf16pair(n2 - __bfloat162float(h2), n3 - __bfloat162float(h3));
    gh.x = bf16pair(q0, q1);
    gh.y = bf16pair(q2, q3);
    ((uint2*)g_neHi4)[bb * 32 + lane] = nh;
    ((uint2*)g_neLo4)[bb * 32 + lane] = nl;
    ((uint2*)g_grHi4)[bb * 32 + lane] = gh;
    __threadfence();                 // every lane: make its stores visible
    __syncwarp();
    if (lane == 0) atomicAdd(&g_prepY[bb >> 7], 1u);
}

// ---------------- single fused kernel ----------------
__global__ __launch_bounds__(NTHR, 1) void k_all(float* __restrict__ out,
                                                 const float* __restrict__ embds,
                                                 const float* __restrict__ w,
                                                 const int* __restrict__ labels) {
    extern __shared__ uint4 smem4[];
    __shared__ float red2[NTHR];
    __shared__ float sinv[128];
    __shared__ float sRow[128];
    __shared__ float sS[128];
    __shared__ int sLb[128];
    __shared__ unsigned int sEpoch;
    const int tid = threadIdx.x;
    const int wid = tid >> 5;
    const int lane = tid & 31;
    const int xb = blockIdx.x;
    const int yb = blockIdx.y;
    const int cBase = xb * 128;
    const int bBase = yb * 128;
    const int cid = yb * 63 + xb;        // 0..125

    if (tid == 0) sEpoch = atomicAdd(&g_entry, 1u) / (unsigned)NCONS;

    // ---- distributed prep FIRST (gather latency overlaps other warps' LDGs)
    if (wid == 0)      prep_row(2 * cid,     lane, embds, w, labels);
    else if (wid == 1) prep_row(2 * cid + 1, lane, embds, w, labels);
    else if (wid == 2 && cid < 4) prep_row(252 + cid, lane, embds, w, labels);

    // ---- load w column chunk straight into registers ----
    const int c = tid & 127;
    const int kq = tid >> 7;            // 0..3
    float wv[32];
    {
        int cCol = cBase + c;
        if (cCol < Cdim) {
            const float* wp = w + (size_t)(kq * 32) * Cdim + cCol;
#pragma unroll
            for (int i = 0; i < 32; i++) wv[i] = wp[(size_t)i * Cdim];
        } else {
#pragma unroll
            for (int i = 0; i < 32; i++) wv[i] = 0.f;
        }
    }

    // ---- w column norm partials ----
    {
        float ss = 0.f;
#pragma unroll
        for (int i = 0; i < 32; i++) ss = fmaf(wv[i], wv[i], ss);
        red2[tid] = ss;
    }
    __syncthreads();
    if (tid < 128) {
        sinv[tid] = rsqrtf(fmaxf(red2[tid] + red2[tid + 128] +
                                 red2[tid + 256] + red2[tid + 384], EPS_F));
        sRow[tid] = 0.f;
    }
    __syncthreads();

    // ---- convert registers -> bf16 hi/lo nw tiles (MMA layout) ----
    {
        float inv = sinv[c];
        uint4* nwHi = smem4 + 3 * TILE_U4;
        uint4* nwLo = smem4 + 4 * TILE_U4;
#pragma unroll
        for (int q = 0; q < 4; q++) {       // 4 16B k-units of 8 bf16
            uint32_t hi[4], lo[4];
#pragma unroll
            for (int uu = 0; uu < 4; uu++) {
                float v0 = wv[q * 8 + uu * 2 + 0] * inv;
                float v1 = wv[q * 8 + uu * 2 + 1] * inv;
                __nv_bfloat16 h0 = __float2bfloat16(v0);
                __nv_bfloat16 h1 = __float2bfloat16(v1);
                hi[uu] = (uint32_t)__bfloat16_as_ushort(h0) |
                         ((uint32_t)__bfloat16_as_ushort(h1) << 16);
                lo[uu] = bf16pair(v0 - __bfloat162float(h0),
                                  v1 - __bfloat162float(h1));
            }
            int kunit = kq * 4 + q;
            nwHi[c * ROW_U4 + kunit] = make_uint4(hi[0], hi[1], hi[2], hi[3]);
            nwLo[c * ROW_U4 + kunit] = make_uint4(lo[0], lo[1], lo[2], lo[3]);
        }
    }

    // ---- wait for THIS y-block's 128 prep rows, then stage ne/gr tiles ----
    unsigned int ep = sEpoch;
    if (tid == 0) {
        unsigned int target = (ep + 1u) * 128u;
        while (*(volatile unsigned int*)&g_prepY[yb] < target) { }
        __threadfence();   // acquire
    }
    __syncthreads();
    {
        const uint4* srcs[3] = {g_neHi4 + bBase * 16, g_neLo4 + bBase * 16,
                                g_grHi4 + bBase * 16};
#pragma unroll
        for (int t3 = 0; t3 < 3; t3++) {
            const uint4* src = srcs[t3];
            uint4* dst = smem4 + t3 * TILE_U4;
#pragma unroll
            for (int i = 0; i < 4; i++) {
                int idx = tid + i * NTHR;
                dst[(idx >> 4) * ROW_U4 + (idx & 15)] = src[idx];
            }
        }
    }
    if (tid < 128) {
        sS[tid] = g_s[bBase + tid];
        sLb[tid] = labels[bBase + tid];
    }
    __syncthreads();

    const uint32_t sb0 = smem_u32(smem4);
    const int m0 = (wid >> 2) * 32;          // warp m-range (b), 4 groups
    const int n0 = (wid & 3) * 32;           // warp n-range (c), 4 groups
    const int rowA = (lane & 7) + ((lane >> 3) & 1) * 8;
    const int uA = lane >> 4;
    const int rowB = (lane & 7) + (lane >> 4) * 8;
    const int uB = (lane >> 3) & 1;

    float accC[2][4][4];
    float accG[2][4][4];
#pragma unroll
    for (int mt = 0; mt < 2; mt++)
#pragma unroll
        for (int j = 0; j < 4; j++)
#pragma unroll
            for (int r = 0; r < 4; r++) { accC[mt][j][r] = 0.f; accG[mt][j][r] = 0.f; }

    // ks-outer loop. cos: 3 split passes (hi*hi, lo*hi, hi*lo). G: hi*hi only
    // (G feeds only rsqrt(2-2G); penalty error < 2e-4 absolute, 5x under gate).
    const uint32_t baseNeHi = sb0;
    const uint32_t baseNeLo = sb0 + (uint32_t)(1 * TILE_U4 * 16);
    const uint32_t baseGrHi = sb0 + (uint32_t)(2 * TILE_U4 * 16);
    const uint32_t baseBHi  = sb0 + (uint32_t)(3 * TILE_U4 * 16);
    const uint32_t baseBLo  = sb0 + (uint32_t)(4 * TILE_U4 * 16);
#pragma unroll
    for (int ks = 0; ks < 8; ks++) {
        uint32_t bfH[4][2], bfL[4][2];
#pragma unroll
        for (int jp = 0; jp < 2; jp++) {
            uint32_t boff =
                (uint32_t)(((n0 + jp * 16 + rowB) * ROW_U4 + ks * 2 + uB) * 16);
            ldsm_x4(bfH[2 * jp][0], bfH[2 * jp][1],
                    bfH[2 * jp + 1][0], bfH[2 * jp + 1][1], baseBHi + boff);
            ldsm_x4(bfL[2 * jp][0], bfL[2 * jp][1],
                    bfL[2 * jp + 1][0], bfL[2 * jp + 1][1], baseBLo + boff);
        }
#pragma unroll
        for (int mt = 0; mt < 2; mt++) {
            uint32_t aoff =
                (uint32_t)(((m0 + mt * 16 + rowA) * ROW_U4 + ks * 2 + uA) * 16);
            uint32_t anH[4], anL[4], agH[4];
            ldsm_x4(anH[0], anH[1], anH[2], anH[3], baseNeHi + aoff);
            ldsm_x4(anL[0], anL[1], anL[2], anL[3], baseNeLo + aoff);
            ldsm_x4(agH[0], agH[1], agH[2], agH[3], baseGrHi + aoff);
#pragma unroll
            for (int j = 0; j < 4; j++) {
                mma16816(accC[mt][j], anH, bfH[j]);
                mma16816(accG[mt][j], agH, bfH[j]);
                mma16816(accC[mt][j], anL, bfH[j]);
                mma16816(accC[mt][j], anH, bfL[j]);
            }
        }
    }

    // ---- epilogue part 1: penalties + exp (kept in accC) + smem rowsums ----
    float* out_logit = out;
    float* out_pen = out + (size_t)Bdim * Cdim;
#pragma unroll
    for (int mt = 0; mt < 2; mt++) {
#pragma unroll
        for (int h = 0; h < 2; h++) {
            int row = m0 + mt * 16 + h * 8 + (lane >> 2);
            int b = bBase + row;
            float sbv = sS[row];
            int lb = sLb[row];
            float esum = 0.f;
#pragma unroll
            for (int j = 0; j < 4; j++) {
                int c0 = cBase + n0 + j * 8 + (lane & 3) * 2;
                if (c0 < Cdim) {   // Cdim even, c0 even -> pair fully valid
                    float cv0 = accC[mt][j][h * 2 + 0];
                    float cv1 = accC[mt][j][h * 2 + 1];
                    float g0 = accG[mt][j][h * 2 + 0];
                    float g1 = accG[mt][j][h * 2 + 1];
                    float w0 = (sbv - cv0) * rsqrtf(fmaxf(2.f - 2.f * g0, EPS_F));
                    float w1 = (sbv - cv1) * rsqrtf(fmaxf(2.f - 2.f * g1, EPS_F));
                    if (c0 == lb) w0 = 0.f;       // dw == 0 exactly in reference
                    if (c0 + 1 == lb) w1 = 0.f;
                    float p0 = MARGIN_F - fminf(MARGIN_F, w0);
                    float p1 = MARGIN_F - fminf(MARGIN_F, w1);
                    float e0 = __expf(SCALE_F * cv0 - SCALE_F);
                    float e1 = __expf(SCALE_F * cv1 - SCALE_F);
                    accC[mt][j][h * 2 + 0] = e0;   // stash ev in registers
                    accC[mt][j][h * 2 + 1] = e1;
                    esum += e0 + e1;
                    *(float2*)&out_pen[(size_t)b * Cdim + c0] = make_float2(p0, p1);
                }
            }
            esum += __shfl_xor_sync(0xffffffffu, esum, 1);
            esum += __shfl_xor_sync(0xffffffffu, esum, 2);
            if ((lane & 3) == 0) atomicAdd(&sRow[row], esum);
        }
    }
    __syncthreads();

    // ---- slot-write partial rowsums, then grid barrier ----
    if (tid < 128) g_part[(yb * 63 + xb) * 128 + tid] = sRow[tid];
    __threadfence();
    __syncthreads();
    if (tid == 0) {
        atomicAdd(&g_bar, 1u);
        unsigned int target = (ep + 1u) * (unsigned)NCONS;
        while (*(volatile unsigned int*)&g_bar < target) { }
    }
    __syncthreads();

    // ---- sum 63 partials per row (unrolled: MLP 15-16) ----
    {
        int row = tid & 127;
        int grp = tid >> 7;               // 0..3: x' ranges of 16,16,16,15
        float s = 0.f;
        if (grp < 3) {
            int x0 = grp * 16;
#pragma unroll
            for (int i = 0; i < 16; i++)
                s += __ldcg(&g_part[(yb * 63 + x0 + i) * 128 + row]);
        } else {
#pragma unroll
            for (int i = 0; i < 15; i++)
                s += __ldcg(&g_part[(yb * 63 + 48 + i) * 128 + row]);
        }
        red2[tid] = s;
    }
    __syncthreads();
    if (tid < 128)
        sRow[tid] = 1.f / (red2[tid] + red2[tid + 128] +
                           red2[tid + 256] + red2[tid + 384]);
    __syncthreads();

    // ---- epilogue part 2: scaled logits ----
#pragma unroll
    for (int mt = 0; mt < 2; mt++) {
#pragma unroll
        for (int h = 0; h < 2; h++) {
            int row = m0 + mt * 16 + h * 8 + (lane >> 2);
            int b = bBase + row;
            float inv = sRow[row];
#pragma unroll
            for (int j = 0; j < 4; j++) {
                int c0 = cBase + n0 + j * 8 + (lane & 3) * 2;
                if (c0 < Cdim) {
                    float e0 = accC[mt][j][h * 2 + 0] * inv;
                    float e1 = accC[mt][j][h * 2 + 1] * inv;
                    *(float2*)&out_logit[(size_t)b * Cdim + c0] =
                        make_float2(e0, e1);
                }
            }
        }
    }
}

// ---------------- launch ----------------
extern "C" void kernel_launch(void* const* d_in, const int* in_sizes, int n_in,
                              void* d_out, int out_size) {
    const float* embds = (const float*)d_in[0];   // [256,128]
    const float* w     = (const float*)d_in[1];   // [128,8000]
    const int* labels  = (const int*)d_in[2];     // [256]
    float* out = (float*)d_out;                   // logits then penalties

    const int kMainSmem = 5 * TILE_U4 * 16;       // 174080 B
    cudaFuncSetAttribute(k_all, cudaFuncAttributeMaxDynamicSharedMemorySize,
                         kMainSmem);

    dim3 g3(63, 2);                               // 126 CTAs, all resident
    k_all<<<g3, NTHR, kMainSmem>>>(out, embds, w, labels);
}